// round 12
// baseline (speedup 1.0000x reference)
#include <cuda_runtime.h>
#include <cuda_fp16.h>
#include <cstdint>
#include <math.h>

// Problem constants
#define B_   4
#define N_   2048
#define D_   1024
#define H_   16
#define HD_  64
#define E3_  192          // 3 * head_dim, chunk order (k, q, v)
#define MROWS (B_ * N_)   // 8192

#define NEG_INF (-1e30f)
#define QSCALE (0.125f * 1.44269504088896f)   // 1/sqrt(64) * log2(e)

// Scratch (allocation-free rule: __device__ globals) — all fp16 operands
__device__ __half g_kqv[(size_t)B_ * H_ * N_ * E3_];   // [b][h][n][e]
__device__ __half g_sa [(size_t)B_ * N_ * D_];         // [b][n][h*hd+d]
__device__ __half g_xt [(size_t)MROWS * D_];           // x -> fp16
__device__ __half g_wt_kqv[(size_t)H_ * E3_ * D_];     // W_kqv^T [h][e][k]
__device__ __half g_wt_proj[(size_t)D_ * D_];          // W_proj^T [n][k]

// ---------------------------------------------------------------------------
// Helpers
// ---------------------------------------------------------------------------
__device__ __forceinline__ float ex2(float x) {
    float y;
    asm("ex2.approx.f32 %0, %1;" : "=f"(y) : "f"(x));
    return y;
}
__device__ __forceinline__ void cpa16(uint32_t dst, const void* src) {
    asm volatile("cp.async.ca.shared.global [%0], [%1], 16;" :: "r"(dst), "l"(src));
}
__device__ __forceinline__ uint32_t smem_u32(const void* p) {
    uint32_t a;
    asm("{ .reg .u64 t; cvta.to.shared.u64 t, %1; cvt.u32.u64 %0, t; }"
        : "=r"(a) : "l"(p));
    return a;
}
__device__ __forceinline__ void mma_f16(float* c, const uint32_t* a, const uint32_t* b) {
    asm volatile(
        "mma.sync.aligned.m16n8k16.row.col.f32.f16.f16.f32 "
        "{%0,%1,%2,%3}, {%4,%5,%6,%7}, {%8,%9}, {%0,%1,%2,%3};"
        : "+f"(c[0]), "+f"(c[1]), "+f"(c[2]), "+f"(c[3])
        : "r"(a[0]), "r"(a[1]), "r"(a[2]), "r"(a[3]), "r"(b[0]), "r"(b[1]));
}
__device__ __forceinline__ void ldsm4(uint32_t* r, uint32_t addr) {
    asm volatile(
        "ldmatrix.sync.aligned.m8n8.x4.shared.b16 {%0,%1,%2,%3}, [%4];"
        : "=r"(r[0]), "=r"(r[1]), "=r"(r[2]), "=r"(r[3]) : "r"(addr));
}
__device__ __forceinline__ void ldsm4t(uint32_t* r, uint32_t addr) {
    asm volatile(
        "ldmatrix.sync.aligned.m8n8.x4.trans.shared.b16 {%0,%1,%2,%3}, [%4];"
        : "=r"(r[0]), "=r"(r[1]), "=r"(r[2]), "=r"(r[3]) : "r"(addr));
}
__device__ __forceinline__ void mbar_wait(uint32_t mbar, uint32_t parity) {
    uint32_t done;
    asm volatile(
        "{\n\t.reg .pred p;\n\t"
        "mbarrier.try_wait.parity.acquire.cta.shared::cta.b64 p, [%1], %2;\n\t"
        "selp.b32 %0, 1, 0, p;\n\t}"
        : "=r"(done) : "r"(mbar), "r"(parity) : "memory");
    while (!done) {
        asm volatile(
            "{\n\t.reg .pred p;\n\t"
            "mbarrier.try_wait.parity.acquire.cta.shared::cta.b64 p, [%1], %2, 0x989680;\n\t"
            "selp.b32 %0, 1, 0, p;\n\t}"
            : "=r"(done) : "r"(mbar), "r"(parity) : "memory");
    }
}

// ---------------------------------------------------------------------------
// Merged prep kernel: fp16-convert x + transpose/convert both weights.
// ---------------------------------------------------------------------------
#define PREP_X   (MROWS * D_ / 1024)          // 8192 blocks
#define PREP_KQV (32 * (E3_ / 32) * H_)       // 3072 blocks
#define PREP_PRJ (32 * 32)                    // 1024 blocks

__global__ void prep_kernel(const float* __restrict__ x,
                            const float* __restrict__ Wkqv,
                            const float* __restrict__ Wproj)
{
    __shared__ float t[32][33];
    const int bx = blockIdx.x, tid = threadIdx.x;
    if (bx < PREP_X) {
        size_t i = ((size_t)bx * 256 + tid) * 4;
        float4 v = *(const float4*)(x + i);
        __half2* dst = (__half2*)(g_xt + i);
        dst[0] = __floats2half2_rn(v.x, v.y);
        dst[1] = __floats2half2_rn(v.z, v.w);
    } else if (bx < PREP_X + PREP_KQV) {
        const int bid = bx - PREP_X;
        const int k0 = (bid & 31) * 32;
        const int e0 = ((bid >> 5) % (E3_ / 32)) * 32;
        const int h  = bid / (32 * (E3_ / 32));
        const float* Wh = Wkqv + (size_t)h * D_ * E3_;
        __half* Wt = g_wt_kqv + (size_t)h * E3_ * D_;
        const int xx = tid & 31, yy = tid >> 5;
#pragma unroll
        for (int j = 0; j < 32; j += 8)
            t[yy + j][xx] = Wh[(size_t)(k0 + yy + j) * E3_ + e0 + xx];
        __syncthreads();
#pragma unroll
        for (int j = 0; j < 32; j += 8)
            Wt[(size_t)(e0 + yy + j) * D_ + k0 + xx] = __float2half_rn(t[xx][yy + j]);
    } else {
        const int bid = bx - PREP_X - PREP_KQV;
        const int k0 = (bid & 31) * 32;
        const int n0 = (bid >> 5) * 32;
        const int xx = tid & 31, yy = tid >> 5;
#pragma unroll
        for (int j = 0; j < 32; j += 8)
            t[yy + j][xx] = Wproj[(size_t)(k0 + yy + j) * D_ + n0 + xx];
        __syncthreads();
#pragma unroll
        for (int j = 0; j < 32; j += 8)
            g_wt_proj[(size_t)(n0 + yy + j) * D_ + k0 + xx] = __float2half_rn(t[xx][yy + j]);
    }
}

// ---------------------------------------------------------------------------
// fp16 mma GEMM, 512 threads (16 warps = 4M x 4N), CTA tile 128 x NT.
// Warp tile 32 x NT/4 -> 4 warps/SMSP for latency hiding.
// K=1024 in chunks of 64 halves; 3-stage cp.async ring; ldmatrix frags.
// ---------------------------------------------------------------------------
template <int NT, int PER_HEAD>
__global__ __launch_bounds__(512, 1) void gemm_mma_kernel(
    const float* __restrict__ bias, float* __restrict__ Cout)
{
    constexpr int NSUBW = NT / 32;       // 8-wide n-subtiles per warp (6 or 4)
    constexpr int AST = 128 * 72;        // halves per A stage
    constexpr int BST = NT * 72;
    extern __shared__ __half smh[];
    __half* As = smh;
    __half* Bs = smh + 3 * AST;

    const int tid  = threadIdx.x;
    const int m0   = blockIdx.x * 128;
    const int head = blockIdx.y;
    const int n0   = PER_HEAD ? 0 : blockIdx.y * NT;

    const __half* Ab = (PER_HEAD ? g_xt : g_sa) + (size_t)m0 * D_;
    const __half* Bt = PER_HEAD ? (g_wt_kqv + (size_t)head * E3_ * D_)
                                : (g_wt_proj + (size_t)n0 * D_);

    const uint32_t sA = smem_u32(As);
    const uint32_t sB = smem_u32(Bs);

    auto load_stage = [&](int kc, int buf) {
        const __half* ap = Ab + kc * 64;
        const uint32_t da = sA + (uint32_t)buf * AST * 2;
#pragma unroll
        for (int j = 0; j < 2; ++j) {                 // 128 rows x 8 x 16B
            const int idx = tid + j * 512;
            const int r = idx >> 3, q = (idx & 7) << 3;
            cpa16(da + (uint32_t)(r * 72 + q) * 2, ap + (size_t)r * D_ + q);
        }
        const __half* bp = Bt + kc * 64;
        const uint32_t db = sB + (uint32_t)buf * BST * 2;
#pragma unroll
        for (int j = 0; j < NT / 64; ++j) {           // NT rows x 8 x 16B
            const int idx = tid + j * 512;
            const int r = idx >> 3, q = (idx & 7) << 3;
            cpa16(db + (uint32_t)(r * 72 + q) * 2, bp + (size_t)r * D_ + q);
        }
    };

    const int w    = tid >> 5, lane = tid & 31;
    const int wm   = (w & 3) * 32;                    // 4 M groups of 32
    const int wn   = (w >> 2) * (NT / 4);             // 4 N groups of NT/4
    const int grp  = lane >> 2, tig = lane & 3;

    const int lrA = ((lane >> 3) & 1) * 8 + (lane & 7);
    const int lcA = ((lane >> 4) & 1) * 8;
    const int lrB = ((lane >> 4) & 1) * 8 + (lane & 7);
    const int lcB = ((lane >> 3) & 1) * 8;

    float acc[2][NSUBW][4];
#pragma unroll
    for (int mi = 0; mi < 2; ++mi)
#pragma unroll
        for (int ni = 0; ni < NSUBW; ++ni)
#pragma unroll
            for (int r = 0; r < 4; ++r) acc[mi][ni][r] = 0.f;

    load_stage(0, 0);
    asm volatile("cp.async.commit_group;" ::: "memory");
    load_stage(1, 1);
    asm volatile("cp.async.commit_group;" ::: "memory");

    for (int kc = 0; kc < 16; ++kc) {
        asm volatile("cp.async.wait_group 1;" ::: "memory");
        __syncthreads();
        if (kc + 2 < 16) load_stage(kc + 2, (kc + 2) % 3);
        asm volatile("cp.async.commit_group;" ::: "memory");

        const int st = kc % 3;
        const uint32_t uAp = sA + (uint32_t)st * AST * 2;
        const uint32_t uBp = sB + (uint32_t)st * BST * 2;
#pragma unroll
        for (int ks = 0; ks < 4; ++ks) {
            const int k = ks * 16;
            uint32_t a[2][4], bf[NSUBW][2];
#pragma unroll
            for (int mi = 0; mi < 2; ++mi)
                ldsm4(a[mi], uAp + (uint32_t)((wm + mi * 16 + lrA) * 72 + k + lcA) * 2);
#pragma unroll
            for (int np = 0; np < NSUBW / 2; ++np) {
                uint32_t r[4];
                ldsm4(r, uBp + (uint32_t)((wn + np * 16 + lrB) * 72 + k + lcB) * 2);
                bf[2 * np][0] = r[0]; bf[2 * np][1] = r[1];
                bf[2 * np + 1][0] = r[2]; bf[2 * np + 1][1] = r[3];
            }
#pragma unroll
            for (int mi = 0; mi < 2; ++mi)
#pragma unroll
                for (int ni = 0; ni < NSUBW; ++ni)
                    mma_f16(acc[mi][ni], a[mi], bf[ni]);
        }
    }

#pragma unroll
    for (int mi = 0; mi < 2; ++mi) {
        const int mbase = m0 + wm + mi * 16 + grp;
#pragma unroll
        for (int half = 0; half < 2; ++half) {
            const int m = mbase + half * 8;
#pragma unroll
            for (int ni = 0; ni < NSUBW; ++ni) {
                const int c = wn + ni * 8 + 2 * tig;
                const float vx = acc[mi][ni][half * 2 + 0];
                const float vy = acc[mi][ni][half * 2 + 1];
                if (PER_HEAD) {
                    const int b = m >> 11, tok = m & 2047;
                    __half* dst = g_kqv + (((size_t)b * H_ + head) * N_ + tok) * E3_;
                    const float* bsp = bias + head * E3_;
                    *(__half2*)(dst + c) =
                        __floats2half2_rn(vx + bsp[c], vy + bsp[c + 1]);
                } else {
                    float* dst = Cout + (size_t)m * D_ + n0;
                    const float* bsp = bias + n0;
                    float2 o; o.x = vx + bsp[c]; o.y = vy + bsp[c + 1];
                    *(float2*)(dst + c) = o;
                }
            }
        }
    }
}

// ---------------------------------------------------------------------------
// fp16 tensor-core causal flash attention (unchanged from R11 passing).
// ---------------------------------------------------------------------------
#define BM 128
#define BK 64
#define KSTH (64 * 72)     // K or V tile (halves)
#define PSTH (128 * 72)    // Q/P buffer (halves)
#define KRING 4
#define VRING 5

__global__ __launch_bounds__(256, 1) void attn_mma_kernel()
{
    extern __shared__ __half smh[];
    const uint32_t sb  = smem_u32(smh);
    const uint32_t uMb = sb;
    const uint32_t uKb = sb + 64;
    const uint32_t uVb = uKb + KRING * KSTH * 2;
    const uint32_t uPq = uVb + VRING * KSTH * 2;
    __half* Pq = smh + (64 + (KRING + VRING) * KSTH * 2) / 2;

    const int qi  = (int)(gridDim.x - 1 - blockIdx.x);
    const int h   = blockIdx.y, b = blockIdx.z;
    const int tid = threadIdx.x;
    const int w   = tid >> 5, lane = tid & 31;
    const int grp = lane >> 2, tig = lane & 3;
    const int m0  = qi * BM;
    const size_t base = ((size_t)b * H_ + h) * N_ * E3_;

    const int lrA = ((lane >> 3) & 1) * 8 + (lane & 7);
    const int lcA = ((lane >> 4) & 1) * 8;
    const int lrB = ((lane >> 4) & 1) * 8 + (lane & 7);
    const int lcB = ((lane >> 3) & 1) * 8;

    const int nt = (m0 + BM) / BK;

    if (tid < KRING) {
        asm volatile("mbarrier.init.shared.b64 [%0], 256;"
                     :: "r"(uMb + (uint32_t)(tid * 8)) : "memory");
    }
    __syncthreads();

    auto load_kv = [&](int kt) {
        const __half* kp = g_kqv + base + (size_t)(kt * BK) * E3_;
        const uint32_t kd = uKb + (uint32_t)(kt % KRING) * KSTH * 2;
#pragma unroll
        for (int j = 0; j < 2; ++j) {
            const int i = tid + j * 256;
            const int n = i >> 3, c = (i & 7) << 3;
            cpa16(kd + (uint32_t)(n * 72 + c) * 2, kp + (size_t)n * E3_ + c);
        }
        const __half* vp = kp + 2 * HD_;
        const uint32_t vd = uVb + (uint32_t)(kt % VRING) * KSTH * 2;
#pragma unroll
        for (int j = 0; j < 2; ++j) {
            const int i = tid + j * 256;
            const int n = i >> 3, c = (i & 7) << 3;
            cpa16(vd + (uint32_t)(n * 72 + c) * 2, vp + (size_t)n * E3_ + c);
        }
        asm volatile("cp.async.mbarrier.arrive.noinc.shared.b64 [%0];"
                     :: "r"(uMb + (uint32_t)((kt % KRING) * 8)) : "memory");
    };

    {
        const __half* q0 = g_kqv + base + (size_t)m0 * E3_ + HD_;
#pragma unroll
        for (int j = 0; j < 4; ++j) {
            const int i = tid + j * 256;
            const int r = i >> 3, c = (i & 7) << 3;
            cpa16(uPq + (uint32_t)(r * 72 + c) * 2, q0 + (size_t)r * E3_ + c);
        }
    }
    load_kv(0);
    if (1 < nt) load_kv(1);
    asm volatile("cp.async.commit_group;" ::: "memory");
    asm volatile("cp.async.wait_group 0;" ::: "memory");
    __syncthreads();

    uint32_t qf[4][4];
    {
        const uint32_t uQw = uPq + (uint32_t)((w * 16 + lrA) * 72) * 2;
#pragma unroll
        for (int ks = 0; ks < 4; ++ks)
            ldsm4(qf[ks], uQw + (uint32_t)(ks * 16 + lcA) * 2);
    }
    __syncthreads();

    const int r0    = m0 + w * 16 + grp;
    const int r1    = r0 + 8;
    const int rmax  = m0 + w * 16 + 15;
    const int diag0 = m0 / BK;

    float oacc[8][4];
#pragma unroll
    for (int ni = 0; ni < 8; ++ni)
#pragma unroll
        for (int r = 0; r < 4; ++r) oacc[ni][r] = 0.f;
    float mr0 = NEG_INF, mr1 = NEG_INF, l0 = 0.f, l1 = 0.f;

    for (int kt = 0; kt < nt; ++kt) {
        if ((kt & 1) == 0) __syncthreads();
        if (kt + 2 < nt) load_kv(kt + 2);
        mbar_wait(uMb + (uint32_t)((kt % KRING) * 8), (uint32_t)((kt >> 2) & 1));

        const bool cur  = (kt * BK <= rmax);
        const bool prev = (kt > 0) && ((kt - 1) * BK <= rmax);

        float s[8][4];
        if (cur) {
            const uint32_t uKp = uKb + (uint32_t)(kt % KRING) * KSTH * 2;
#pragma unroll
            for (int ni = 0; ni < 8; ++ni)
#pragma unroll
                for (int r = 0; r < 4; ++r) s[ni][r] = 0.f;
#pragma unroll
            for (int ks = 0; ks < 4; ++ks) {
                const int k = ks * 16;
                uint32_t bf[8][2];
#pragma unroll
                for (int np = 0; np < 4; ++np) {
                    uint32_t r[4];
                    ldsm4(r, uKp + (uint32_t)((np * 16 + lrB) * 72 + k + lcB) * 2);
                    bf[2 * np][0] = r[0]; bf[2 * np][1] = r[1];
                    bf[2 * np + 1][0] = r[2]; bf[2 * np + 1][1] = r[3];
                }
#pragma unroll
                for (int ni = 0; ni < 8; ++ni)
                    mma_f16(s[ni], qf[ks], bf[ni]);
            }
        }

        if (prev) {
            const uint32_t uVp = uVb + (uint32_t)((kt - 1) % VRING) * KSTH * 2;
            const uint32_t uPp = uPq + (uint32_t)((kt - 1) & 1) * PSTH * 2
                               + (uint32_t)((w * 16 + lrA) * 72) * 2;
#pragma unroll
            for (int ks = 0; ks < 4; ++ks) {
                const int k = ks * 16;
                uint32_t a[4];
                ldsm4(a, uPp + (uint32_t)(k + lcA) * 2);
                uint32_t bf[8][2];
#pragma unroll
                for (int np = 0; np < 4; ++np) {
                    uint32_t r[4];
                    ldsm4t(r, uVp + (uint32_t)((k + lrA) * 72 + np * 16 + lcA) * 2);
                    bf[2 * np][0] = r[0]; bf[2 * np][1] = r[1];
                    bf[2 * np + 1][0] = r[2]; bf[2 * np + 1][1] = r[3];
                }
#pragma unroll
                for (int ni = 0; ni < 8; ++ni)
                    mma_f16(oacc[ni], a, bf[ni]);
            }
        }

        if (cur) {
            if (kt >= diag0) {
                const int colb = kt * BK;
#pragma unroll
                for (int ni = 0; ni < 8; ++ni) {
                    const int c = colb + ni * 8 + 2 * tig;
                    if (c > r0)     s[ni][0] = NEG_INF;
                    if (c + 1 > r0) s[ni][1] = NEG_INF;
                    if (c > r1)     s[ni][2] = NEG_INF;
                    if (c + 1 > r1) s[ni][3] = NEG_INF;
                }
            }

            float mx0 = NEG_INF, mx1 = NEG_INF;
#pragma unroll
            for (int ni = 0; ni < 8; ++ni) {
                mx0 = fmaxf(mx0, fmaxf(s[ni][0], s[ni][1]));
                mx1 = fmaxf(mx1, fmaxf(s[ni][2], s[ni][3]));
            }
            mx0 = fmaxf(mx0, __shfl_xor_sync(0xffffffffu, mx0, 1));
            mx0 = fmaxf(mx0, __shfl_xor_sync(0xffffffffu, mx0, 2));
            mx1 = fmaxf(mx1, __shfl_xor_sync(0xffffffffu, mx1, 1));
            mx1 = fmaxf(mx1, __shfl_xor_sync(0xffffffffu, mx1, 2));

            const float mn0 = fmaxf(mr0, mx0 * QSCALE);
            const float mn1 = fmaxf(mr1, mx1 * QSCALE);
            const float a0 = ex2(mr0 - mn0), a1 = ex2(mr1 - mn1);
            float sum0 = 0.f, sum1 = 0.f;
#pragma unroll
            for (int ni = 0; ni < 8; ++ni) {
                s[ni][0] = ex2(fmaf(s[ni][0], QSCALE, -mn0));
                s[ni][1] = ex2(fmaf(s[ni][1], QSCALE, -mn0));
                s[ni][2] = ex2(fmaf(s[ni][2], QSCALE, -mn1));
                s[ni][3] = ex2(fmaf(s[ni][3], QSCALE, -mn1));
                sum0 += s[ni][0] + s[ni][1];
                sum1 += s[ni][2] + s[ni][3];
            }
            sum0 += __shfl_xor_sync(0xffffffffu, sum0, 1);
            sum0 += __shfl_xor_sync(0xffffffffu, sum0, 2);
            sum1 += __shfl_xor_sync(0xffffffffu, sum1, 1);
            sum1 += __shfl_xor_sync(0xffffffffu, sum1, 2);

            l0 = l0 * a0 + sum0;  mr0 = mn0;
            l1 = l1 * a1 + sum1;  mr1 = mn1;
#pragma unroll
            for (int ni = 0; ni < 8; ++ni) {
                oacc[ni][0] *= a0; oacc[ni][1] *= a0;
                oacc[ni][2] *= a1; oacc[ni][3] *= a1;
            }

            __half* prow0 = Pq + (kt & 1) * PSTH + (w * 16 + grp) * 72;
            __half* prow1 = prow0 + 8 * 72;
#pragma unroll
            for (int ni = 0; ni < 8; ++ni) {
                const int c = ni * 8 + 2 * tig;
                *(__half2*)(prow0 + c) = __floats2half2_rn(s[ni][0], s[ni][1]);
                *(__half2*)(prow1 + c) = __floats2half2_rn(s[ni][2], s[ni][3]);
            }
            __syncwarp();
        }
    }

    if ((nt - 1) * BK <= rmax) {
        const int kt = nt - 1;
        const uint32_t uVp = uVb + (uint32_t)(kt % VRING) * KSTH * 2;
        const uint32_t uPp = uPq + (uint32_t)(kt & 1) * PSTH * 2
                           + (uint32_t)((w * 16 + lrA) * 72) * 2;
#pragma unroll
        for (int ks = 0; ks < 4; ++ks) {
            const int k = ks * 16;
            uint32_t a[4];
            ldsm4(a, uPp + (uint32_t)(k + lcA) * 2);
            uint32_t bf[8][2];
#pragma unroll
            for (int np = 0; np < 4; ++np) {
                uint32_t r[4];
                ldsm4t(r, uVp + (uint32_t)((k + lrA) * 72 + np * 16 + lcA) * 2);
                bf[2 * np][0] = r[0]; bf[2 * np][1] = r[1];
                bf[2 * np + 1][0] = r[2]; bf[2 * np + 1][1] = r[3];
            }
#pragma unroll
            for (int ni = 0; ni < 8; ++ni)
                mma_f16(oacc[ni], a, bf[ni]);
        }
    }

    const float inv0 = 1.0f / l0, inv1 = 1.0f / l1;
    __half* d0 = g_sa + ((size_t)b * N_ + r0) * D_ + h * HD_;
    __half* d1 = g_sa + ((size_t)b * N_ + r1) * D_ + h * HD_;
#pragma unroll
    for (int ni = 0; ni < 8; ++ni) {
        const int c = ni * 8 + 2 * tig;
        *(__half2*)(d0 + c) = __floats2half2_rn(oacc[ni][0] * inv0, oacc[ni][1] * inv0);
        *(__half2*)(d1 + c) = __floats2half2_rn(oacc[ni][2] * inv1, oacc[ni][3] * inv1);
    }
}

// ---------------------------------------------------------------------------
extern "C" void kernel_launch(void* const* d_in, const int* in_sizes, int n_in,
                              void* d_out, int out_size)
{
    const float* x      = (const float*)d_in[0];
    const float* W_kqv  = (const float*)d_in[1];
    const float* b_kqv  = (const float*)d_in[2];
    const float* W_proj = (const float*)d_in[3];
    const float* b_proj = (const float*)d_in[4];
    float* out = (float*)d_out;

    const int SMEM_Q = 3 * (128 + E3_) * 72 * 2;                 // 138240
    const int SMEM_P = 3 * (128 + 128) * 72 * 2;                 // 110592
    const int SMEM_A = 64 + ((KRING + VRING) * KSTH + 2 * PSTH) * 2;  // 202816
    cudaFuncSetAttribute(gemm_mma_kernel<E3_, 1>,
                         cudaFuncAttributeMaxDynamicSharedMemorySize, SMEM_Q);
    cudaFuncSetAttribute(gemm_mma_kernel<128, 0>,
                         cudaFuncAttributeMaxDynamicSharedMemorySize, SMEM_P);
    cudaFuncSetAttribute(attn_mma_kernel,
                         cudaFuncAttributeMaxDynamicSharedMemorySize, SMEM_A);

    prep_kernel<<<PREP_X + PREP_KQV + PREP_PRJ, 256>>>(x, W_kqv, W_proj);

    gemm_mma_kernel<E3_, 1><<<dim3(MROWS / 128, H_), 512, SMEM_Q>>>(b_kqv, nullptr);
    attn_mma_kernel<<<dim3(N_ / BM, H_, B_), 256, SMEM_A>>>();
    gemm_mma_kernel<128, 0><<<dim3(MROWS / 128, D_ / 128), 512, SMEM_P>>>(b_proj, out);
}

// round 13
// speedup vs baseline: 1.0761x; 1.0761x over previous
#include <cuda_runtime.h>
#include <cuda_fp16.h>
#include <cstdint>
#include <math.h>

// Problem constants
#define B_   4
#define N_   2048
#define D_   1024
#define H_   16
#define HD_  64
#define E3_  192          // 3 * head_dim, chunk order (k, q, v)
#define MROWS (B_ * N_)   // 8192

#define NEG_INF (-1e30f)
#define QSCALE (0.125f * 1.44269504088896f)   // 1/sqrt(64) * log2(e)

// Scratch (allocation-free rule: __device__ globals) — all fp16 operands
__device__ __half g_kqv[(size_t)B_ * H_ * N_ * E3_];   // [b][h][n][e]
__device__ __half g_sa [(size_t)B_ * N_ * D_];         // [b][n][h*hd+d]
__device__ __half g_xt [(size_t)MROWS * D_];           // x -> fp16
__device__ __half g_wt_kqv[(size_t)H_ * E3_ * D_];     // W_kqv^T [h][e][k]
__device__ __half g_wt_proj[(size_t)D_ * D_];          // W_proj^T [n][k]

// ---------------------------------------------------------------------------
// Helpers
// ---------------------------------------------------------------------------
__device__ __forceinline__ float ex2(float x) {
    float y;
    asm("ex2.approx.f32 %0, %1;" : "=f"(y) : "f"(x));
    return y;
}
__device__ __forceinline__ void cpa16(uint32_t dst, const void* src) {
    asm volatile("cp.async.ca.shared.global [%0], [%1], 16;" :: "r"(dst), "l"(src));
}
__device__ __forceinline__ uint32_t smem_u32(const void* p) {
    uint32_t a;
    asm("{ .reg .u64 t; cvta.to.shared.u64 t, %1; cvt.u32.u64 %0, t; }"
        : "=r"(a) : "l"(p));
    return a;
}
__device__ __forceinline__ void mma_f16(float* c, const uint32_t* a, const uint32_t* b) {
    asm volatile(
        "mma.sync.aligned.m16n8k16.row.col.f32.f16.f16.f32 "
        "{%0,%1,%2,%3}, {%4,%5,%6,%7}, {%8,%9}, {%0,%1,%2,%3};"
        : "+f"(c[0]), "+f"(c[1]), "+f"(c[2]), "+f"(c[3])
        : "r"(a[0]), "r"(a[1]), "r"(a[2]), "r"(a[3]), "r"(b[0]), "r"(b[1]));
}
__device__ __forceinline__ void ldsm4(uint32_t* r, uint32_t addr) {
    asm volatile(
        "ldmatrix.sync.aligned.m8n8.x4.shared.b16 {%0,%1,%2,%3}, [%4];"
        : "=r"(r[0]), "=r"(r[1]), "=r"(r[2]), "=r"(r[3]) : "r"(addr));
}
__device__ __forceinline__ void ldsm4t(uint32_t* r, uint32_t addr) {
    asm volatile(
        "ldmatrix.sync.aligned.m8n8.x4.trans.shared.b16 {%0,%1,%2,%3}, [%4];"
        : "=r"(r[0]), "=r"(r[1]), "=r"(r[2]), "=r"(r[3]) : "r"(addr));
}
__device__ __forceinline__ uint32_t packh2(float x, float y) {
    __half2 h = __floats2half2_rn(x, y);
    return *(uint32_t*)&h;
}
__device__ __forceinline__ void mbar_wait(uint32_t mbar, uint32_t parity) {
    uint32_t done;
    asm volatile(
        "{\n\t.reg .pred p;\n\t"
        "mbarrier.try_wait.parity.acquire.cta.shared::cta.b64 p, [%1], %2;\n\t"
        "selp.b32 %0, 1, 0, p;\n\t}"
        : "=r"(done) : "r"(mbar), "r"(parity) : "memory");
    while (!done) {
        asm volatile(
            "{\n\t.reg .pred p;\n\t"
            "mbarrier.try_wait.parity.acquire.cta.shared::cta.b64 p, [%1], %2, 0x989680;\n\t"
            "selp.b32 %0, 1, 0, p;\n\t}"
            : "=r"(done) : "r"(mbar), "r"(parity) : "memory");
    }
}

// ---------------------------------------------------------------------------
// Merged prep kernel: fp16-convert x + transpose/convert both weights.
// ---------------------------------------------------------------------------
#define PREP_X   (MROWS * D_ / 1024)          // 8192 blocks
#define PREP_KQV (32 * (E3_ / 32) * H_)       // 3072 blocks
#define PREP_PRJ (32 * 32)                    // 1024 blocks

__global__ void prep_kernel(const float* __restrict__ x,
                            const float* __restrict__ Wkqv,
                            const float* __restrict__ Wproj)
{
    __shared__ float t[32][33];
    const int bx = blockIdx.x, tid = threadIdx.x;
    if (bx < PREP_X) {
        size_t i = ((size_t)bx * 256 + tid) * 4;
        float4 v = *(const float4*)(x + i);
        __half2* dst = (__half2*)(g_xt + i);
        dst[0] = __floats2half2_rn(v.x, v.y);
        dst[1] = __floats2half2_rn(v.z, v.w);
    } else if (bx < PREP_X + PREP_KQV) {
        const int bid = bx - PREP_X;
        const int k0 = (bid & 31) * 32;
        const int e0 = ((bid >> 5) % (E3_ / 32)) * 32;
        const int h  = bid / (32 * (E3_ / 32));
        const float* Wh = Wkqv + (size_t)h * D_ * E3_;
        __half* Wt = g_wt_kqv + (size_t)h * E3_ * D_;
        const int xx = tid & 31, yy = tid >> 5;
#pragma unroll
        for (int j = 0; j < 32; j += 8)
            t[yy + j][xx] = Wh[(size_t)(k0 + yy + j) * E3_ + e0 + xx];
        __syncthreads();
#pragma unroll
        for (int j = 0; j < 32; j += 8)
            Wt[(size_t)(e0 + yy + j) * D_ + k0 + xx] = __float2half_rn(t[xx][yy + j]);
    } else {
        const int bid = bx - PREP_X - PREP_KQV;
        const int k0 = (bid & 31) * 32;
        const int n0 = (bid >> 5) * 32;
        const int xx = tid & 31, yy = tid >> 5;
#pragma unroll
        for (int j = 0; j < 32; j += 8)
            t[yy + j][xx] = Wproj[(size_t)(k0 + yy + j) * D_ + n0 + xx];
        __syncthreads();
#pragma unroll
        for (int j = 0; j < 32; j += 8)
            g_wt_proj[(size_t)(n0 + yy + j) * D_ + k0 + xx] = __float2half_rn(t[xx][yy + j]);
    }
}

// ---------------------------------------------------------------------------
// fp16 mma GEMM, 512 threads (16 warps = 4M x 4N), CTA tile 128 x NT.
// (unchanged from R12)
// ---------------------------------------------------------------------------
template <int NT, int PER_HEAD>
__global__ __launch_bounds__(512, 1) void gemm_mma_kernel(
    const float* __restrict__ bias, float* __restrict__ Cout)
{
    constexpr int NSUBW = NT / 32;
    constexpr int AST = 128 * 72;
    constexpr int BST = NT * 72;
    extern __shared__ __half smh[];
    __half* As = smh;
    __half* Bs = smh + 3 * AST;

    const int tid  = threadIdx.x;
    const int m0   = blockIdx.x * 128;
    const int head = blockIdx.y;
    const int n0   = PER_HEAD ? 0 : blockIdx.y * NT;

    const __half* Ab = (PER_HEAD ? g_xt : g_sa) + (size_t)m0 * D_;
    const __half* Bt = PER_HEAD ? (g_wt_kqv + (size_t)head * E3_ * D_)
                                : (g_wt_proj + (size_t)n0 * D_);

    const uint32_t sA = smem_u32(As);
    const uint32_t sB = smem_u32(Bs);

    auto load_stage = [&](int kc, int buf) {
        const __half* ap = Ab + kc * 64;
        const uint32_t da = sA + (uint32_t)buf * AST * 2;
#pragma unroll
        for (int j = 0; j < 2; ++j) {
            const int idx = tid + j * 512;
            const int r = idx >> 3, q = (idx & 7) << 3;
            cpa16(da + (uint32_t)(r * 72 + q) * 2, ap + (size_t)r * D_ + q);
        }
        const __half* bp = Bt + kc * 64;
        const uint32_t db = sB + (uint32_t)buf * BST * 2;
#pragma unroll
        for (int j = 0; j < NT / 64; ++j) {
            const int idx = tid + j * 512;
            const int r = idx >> 3, q = (idx & 7) << 3;
            cpa16(db + (uint32_t)(r * 72 + q) * 2, bp + (size_t)r * D_ + q);
        }
    };

    const int w    = tid >> 5, lane = tid & 31;
    const int wm   = (w & 3) * 32;
    const int wn   = (w >> 2) * (NT / 4);
    const int grp  = lane >> 2, tig = lane & 3;

    const int lrA = ((lane >> 3) & 1) * 8 + (lane & 7);
    const int lcA = ((lane >> 4) & 1) * 8;
    const int lrB = ((lane >> 4) & 1) * 8 + (lane & 7);
    const int lcB = ((lane >> 3) & 1) * 8;

    float acc[2][NSUBW][4];
#pragma unroll
    for (int mi = 0; mi < 2; ++mi)
#pragma unroll
        for (int ni = 0; ni < NSUBW; ++ni)
#pragma unroll
            for (int r = 0; r < 4; ++r) acc[mi][ni][r] = 0.f;

    load_stage(0, 0);
    asm volatile("cp.async.commit_group;" ::: "memory");
    load_stage(1, 1);
    asm volatile("cp.async.commit_group;" ::: "memory");

    for (int kc = 0; kc < 16; ++kc) {
        asm volatile("cp.async.wait_group 1;" ::: "memory");
        __syncthreads();
        if (kc + 2 < 16) load_stage(kc + 2, (kc + 2) % 3);
        asm volatile("cp.async.commit_group;" ::: "memory");

        const int st = kc % 3;
        const uint32_t uAp = sA + (uint32_t)st * AST * 2;
        const uint32_t uBp = sB + (uint32_t)st * BST * 2;
#pragma unroll
        for (int ks = 0; ks < 4; ++ks) {
            const int k = ks * 16;
            uint32_t a[2][4], bf[NSUBW][2];
#pragma unroll
            for (int mi = 0; mi < 2; ++mi)
                ldsm4(a[mi], uAp + (uint32_t)((wm + mi * 16 + lrA) * 72 + k + lcA) * 2);
#pragma unroll
            for (int np = 0; np < NSUBW / 2; ++np) {
                uint32_t r[4];
                ldsm4(r, uBp + (uint32_t)((wn + np * 16 + lrB) * 72 + k + lcB) * 2);
                bf[2 * np][0] = r[0]; bf[2 * np][1] = r[1];
                bf[2 * np + 1][0] = r[2]; bf[2 * np + 1][1] = r[3];
            }
#pragma unroll
            for (int mi = 0; mi < 2; ++mi)
#pragma unroll
                for (int ni = 0; ni < NSUBW; ++ni)
                    mma_f16(acc[mi][ni], a[mi], bf[ni]);
        }
    }

#pragma unroll
    for (int mi = 0; mi < 2; ++mi) {
        const int mbase = m0 + wm + mi * 16 + grp;
#pragma unroll
        for (int half = 0; half < 2; ++half) {
            const int m = mbase + half * 8;
#pragma unroll
            for (int ni = 0; ni < NSUBW; ++ni) {
                const int c = wn + ni * 8 + 2 * tig;
                const float vx = acc[mi][ni][half * 2 + 0];
                const float vy = acc[mi][ni][half * 2 + 1];
                if (PER_HEAD) {
                    const int b = m >> 11, tok = m & 2047;
                    __half* dst = g_kqv + (((size_t)b * H_ + head) * N_ + tok) * E3_;
                    const float* bsp = bias + head * E3_;
                    *(__half2*)(dst + c) =
                        __floats2half2_rn(vx + bsp[c], vy + bsp[c + 1]);
                } else {
                    float* dst = Cout + (size_t)m * D_ + n0;
                    const float* bsp = bias + n0;
                    float2 o; o.x = vx + bsp[c]; o.y = vy + bsp[c + 1];
                    *(float2*)(dst + c) = o;
                }
            }
        }
    }
}

// ---------------------------------------------------------------------------
// fp16 tensor-core causal flash attention — REGISTER-P (FA2 style).
// S C-fragments are repacked in registers as PV A-fragments (identical
// layout), so P never touches smem: no P store/ldmatrix, no deferred PV.
// K,V rings of 4 with per-slot mbarriers; CTA barrier every 2nd tile
// bounds drift <=1 (write (kt+2)%4 vs reads kt%4/(kt-1)%4 -> dist 2,3).
// ---------------------------------------------------------------------------
#define BM 128
#define BK 64
#define KSTH (64 * 72)     // K or V tile (halves)
#define QSTH (128 * 72)    // Q staging (halves)
#define KRING 4
#define VRING 4

__global__ __launch_bounds__(256, 1) void attn_mma_kernel()
{
    extern __shared__ __half smh[];
    const uint32_t sb  = smem_u32(smh);
    const uint32_t uMb = sb;                         // 4 mbarriers
    const uint32_t uKb = sb + 64;                    // [KRING][KSTH]
    const uint32_t uVb = uKb + KRING * KSTH * 2;     // [VRING][KSTH]
    const uint32_t uQ  = uVb + VRING * KSTH * 2;     // [QSTH]

    const int qi  = (int)(gridDim.x - 1 - blockIdx.x);  // heavy tiles first
    const int h   = blockIdx.y, b = blockIdx.z;
    const int tid = threadIdx.x;
    const int w   = tid >> 5, lane = tid & 31;
    const int grp = lane >> 2, tig = lane & 3;
    const int m0  = qi * BM;
    const size_t base = ((size_t)b * H_ + h) * N_ * E3_;

    const int lrA = ((lane >> 3) & 1) * 8 + (lane & 7);
    const int lcA = ((lane >> 4) & 1) * 8;
    const int lrB = ((lane >> 4) & 1) * 8 + (lane & 7);
    const int lcB = ((lane >> 3) & 1) * 8;

    const int nt = (m0 + BM) / BK;

    if (tid < KRING) {
        asm volatile("mbarrier.init.shared.b64 [%0], 256;"
                     :: "r"(uMb + (uint32_t)(tid * 8)) : "memory");
    }
    __syncthreads();

    auto load_kv = [&](int kt) {
        const __half* kp = g_kqv + base + (size_t)(kt * BK) * E3_;
        const uint32_t kd = uKb + (uint32_t)(kt % KRING) * KSTH * 2;
#pragma unroll
        for (int j = 0; j < 2; ++j) {
            const int i = tid + j * 256;
            const int n = i >> 3, c = (i & 7) << 3;
            cpa16(kd + (uint32_t)(n * 72 + c) * 2, kp + (size_t)n * E3_ + c);
        }
        const __half* vp = kp + 2 * HD_;
        const uint32_t vd = uVb + (uint32_t)(kt % VRING) * KSTH * 2;
#pragma unroll
        for (int j = 0; j < 2; ++j) {
            const int i = tid + j * 256;
            const int n = i >> 3, c = (i & 7) << 3;
            cpa16(vd + (uint32_t)(n * 72 + c) * 2, vp + (size_t)n * E3_ + c);
        }
        asm volatile("cp.async.mbarrier.arrive.noinc.shared.b64 [%0];"
                     :: "r"(uMb + (uint32_t)((kt % KRING) * 8)) : "memory");
    };

    // Stage Q (128 x 64 halves) + prefetch tiles 0,1
    {
        const __half* q0 = g_kqv + base + (size_t)m0 * E3_ + HD_;
#pragma unroll
        for (int j = 0; j < 4; ++j) {
            const int i = tid + j * 256;
            const int r = i >> 3, c = (i & 7) << 3;
            cpa16(uQ + (uint32_t)(r * 72 + c) * 2, q0 + (size_t)r * E3_ + c);
        }
    }
    load_kv(0);
    if (1 < nt) load_kv(1);
    asm volatile("cp.async.commit_group;" ::: "memory");
    asm volatile("cp.async.wait_group 0;" ::: "memory");
    __syncthreads();

    // Q fragments (unscaled) in registers for the whole kernel
    uint32_t qf[4][4];
    {
        const uint32_t uQw = uQ + (uint32_t)((w * 16 + lrA) * 72) * 2;
#pragma unroll
        for (int ks = 0; ks < 4; ++ks)
            ldsm4(qf[ks], uQw + (uint32_t)(ks * 16 + lcA) * 2);
    }

    const int r0    = m0 + w * 16 + grp;
    const int r1    = r0 + 8;
    const int rmax  = m0 + w * 16 + 15;
    const int diag0 = m0 / BK;

    float oacc[8][4];
#pragma unroll
    for (int ni = 0; ni < 8; ++ni)
#pragma unroll
        for (int r = 0; r < 4; ++r) oacc[ni][r] = 0.f;
    float mr0 = NEG_INF, mr1 = NEG_INF, l0 = 0.f, l1 = 0.f;

    for (int kt = 0; kt < nt; ++kt) {
        if ((kt & 1) == 0) __syncthreads();   // bound warp drift <= 1 iter
        if (kt + 2 < nt) load_kv(kt + 2);
        mbar_wait(uMb + (uint32_t)((kt % KRING) * 8), (uint32_t)((kt >> 2) & 1));

        if (kt * BK > rmax) continue;   // fully masked tile

        // S = Q K^T
        const uint32_t uKp = uKb + (uint32_t)(kt % KRING) * KSTH * 2;
        float s[8][4];
#pragma unroll
        for (int ni = 0; ni < 8; ++ni)
#pragma unroll
            for (int r = 0; r < 4; ++r) s[ni][r] = 0.f;
#pragma unroll
        for (int ks = 0; ks < 4; ++ks) {
            const int k = ks * 16;
            uint32_t bf[8][2];
#pragma unroll
            for (int np = 0; np < 4; ++np) {
                uint32_t r[4];
                ldsm4(r, uKp + (uint32_t)((np * 16 + lrB) * 72 + k + lcB) * 2);
                bf[2 * np][0] = r[0]; bf[2 * np][1] = r[1];
                bf[2 * np + 1][0] = r[2]; bf[2 * np + 1][1] = r[3];
            }
#pragma unroll
            for (int ni = 0; ni < 8; ++ni)
                mma_f16(s[ni], qf[ks], bf[ni]);
        }

        // Causal mask (diagonal-overlapping tiles only)
        if (kt >= diag0) {
            const int colb = kt * BK;
#pragma unroll
            for (int ni = 0; ni < 8; ++ni) {
                const int c = colb + ni * 8 + 2 * tig;
                if (c > r0)     s[ni][0] = NEG_INF;
                if (c + 1 > r0) s[ni][1] = NEG_INF;
                if (c > r1)     s[ni][2] = NEG_INF;
                if (c + 1 > r1) s[ni][3] = NEG_INF;
            }
        }

        // Online softmax (rows r0, r1); quad reduction over 4 lanes
        float mx0 = NEG_INF, mx1 = NEG_INF;
#pragma unroll
        for (int ni = 0; ni < 8; ++ni) {
            mx0 = fmaxf(mx0, fmaxf(s[ni][0], s[ni][1]));
            mx1 = fmaxf(mx1, fmaxf(s[ni][2], s[ni][3]));
        }
        mx0 = fmaxf(mx0, __shfl_xor_sync(0xffffffffu, mx0, 1));
        mx0 = fmaxf(mx0, __shfl_xor_sync(0xffffffffu, mx0, 2));
        mx1 = fmaxf(mx1, __shfl_xor_sync(0xffffffffu, mx1, 1));
        mx1 = fmaxf(mx1, __shfl_xor_sync(0xffffffffu, mx1, 2));

        const float mn0 = fmaxf(mr0, mx0 * QSCALE);
        const float mn1 = fmaxf(mr1, mx1 * QSCALE);
        const float a0 = ex2(mr0 - mn0), a1 = ex2(mr1 - mn1);
        float sum0 = 0.f, sum1 = 0.f;
#pragma unroll
        for (int ni = 0; ni < 8; ++ni) {
            s[ni][0] = ex2(fmaf(s[ni][0], QSCALE, -mn0));
            s[ni][1] = ex2(fmaf(s[ni][1], QSCALE, -mn0));
            s[ni][2] = ex2(fmaf(s[ni][2], QSCALE, -mn1));
            s[ni][3] = ex2(fmaf(s[ni][3], QSCALE, -mn1));
            sum0 += s[ni][0] + s[ni][1];
            sum1 += s[ni][2] + s[ni][3];
        }
        sum0 += __shfl_xor_sync(0xffffffffu, sum0, 1);
        sum0 += __shfl_xor_sync(0xffffffffu, sum0, 2);
        sum1 += __shfl_xor_sync(0xffffffffu, sum1, 1);
        sum1 += __shfl_xor_sync(0xffffffffu, sum1, 2);

        l0 = l0 * a0 + sum0;  mr0 = mn0;
        l1 = l1 * a1 + sum1;  mr1 = mn1;
#pragma unroll
        for (int ni = 0; ni < 8; ++ni) {
            oacc[ni][0] *= a0; oacc[ni][1] *= a0;
            oacc[ni][2] *= a1; oacc[ni][3] *= a1;
        }

        // O += P V : P A-fragments built in registers from S C-fragments
        const uint32_t uVp = uVb + (uint32_t)(kt % VRING) * KSTH * 2;
#pragma unroll
        for (int ks = 0; ks < 4; ++ks) {
            const int k = ks * 16;
            uint32_t a[4];
            a[0] = packh2(s[2 * ks][0],     s[2 * ks][1]);
            a[1] = packh2(s[2 * ks][2],     s[2 * ks][3]);
            a[2] = packh2(s[2 * ks + 1][0], s[2 * ks + 1][1]);
            a[3] = packh2(s[2 * ks + 1][2], s[2 * ks + 1][3]);
            uint32_t bf[8][2];
#pragma unroll
            for (int np = 0; np < 4; ++np) {
                uint32_t r[4];
                ldsm4t(r, uVp + (uint32_t)((k + lrA) * 72 + np * 16 + lcA) * 2);
                bf[2 * np][0] = r[0]; bf[2 * np][1] = r[1];
                bf[2 * np + 1][0] = r[2]; bf[2 * np + 1][1] = r[3];
            }
#pragma unroll
            for (int ni = 0; ni < 8; ++ni)
                mma_f16(oacc[ni], a, bf[ni]);
        }
    }

    // Epilogue: normalize, fp16-store (proj GEMM consumes g_sa)
    const float inv0 = 1.0f / l0, inv1 = 1.0f / l1;
    __half* d0 = g_sa + ((size_t)b * N_ + r0) * D_ + h * HD_;
    __half* d1 = g_sa + ((size_t)b * N_ + r1) * D_ + h * HD_;
#pragma unroll
    for (int ni = 0; ni < 8; ++ni) {
        const int c = ni * 8 + 2 * tig;
        *(__half2*)(d0 + c) = __floats2half2_rn(oacc[ni][0] * inv0, oacc[ni][1] * inv0);
        *(__half2*)(d1 + c) = __floats2half2_rn(oacc[ni][2] * inv1, oacc[ni][3] * inv1);
    }
}

// ---------------------------------------------------------------------------
extern "C" void kernel_launch(void* const* d_in, const int* in_sizes, int n_in,
                              void* d_out, int out_size)
{
    const float* x      = (const float*)d_in[0];
    const float* W_kqv  = (const float*)d_in[1];
    const float* b_kqv  = (const float*)d_in[2];
    const float* W_proj = (const float*)d_in[3];
    const float* b_proj = (const float*)d_in[4];
    float* out = (float*)d_out;

    const int SMEM_Q = 3 * (128 + E3_) * 72 * 2;                     // 138240
    const int SMEM_P = 3 * (128 + 128) * 72 * 2;                     // 110592
    const int SMEM_A = 64 + ((KRING + VRING) * KSTH + QSTH) * 2;     // 92224
    cudaFuncSetAttribute(gemm_mma_kernel<E3_, 1>,
                         cudaFuncAttributeMaxDynamicSharedMemorySize, SMEM_Q);
    cudaFuncSetAttribute(gemm_mma_kernel<128, 0>,
                         cudaFuncAttributeMaxDynamicSharedMemorySize, SMEM_P);
    cudaFuncSetAttribute(attn_mma_kernel,
                         cudaFuncAttributeMaxDynamicSharedMemorySize, SMEM_A);

    prep_kernel<<<PREP_X + PREP_KQV + PREP_PRJ, 256>>>(x, W_kqv, W_proj);

    gemm_mma_kernel<E3_, 1><<<dim3(MROWS / 128, H_), 512, SMEM_Q>>>(b_kqv, nullptr);
    attn_mma_kernel<<<dim3(N_ / BM, H_, B_), 256, SMEM_A>>>();
    gemm_mma_kernel<128, 0><<<dim3(MROWS / 128, D_ / 128), 512, SMEM_P>>>(b_proj, out);
}

// round 14
// speedup vs baseline: 1.1346x; 1.0544x over previous
#include <cuda_runtime.h>
#include <cuda_fp16.h>
#include <cstdint>
#include <math.h>

// Problem constants
#define B_   4
#define N_   2048
#define D_   1024
#define H_   16
#define HD_  64
#define E3_  192          // 3 * head_dim, chunk order (k, q, v)
#define MROWS (B_ * N_)   // 8192

#define NEG_INF (-1e30f)
#define QSCALE (0.125f * 1.44269504088896f)   // 1/sqrt(64) * log2(e)

// Scratch (allocation-free rule: __device__ globals) — all fp16 operands
__device__ __half g_kqv[(size_t)B_ * H_ * N_ * E3_];   // [b][h][n][e]
__device__ __half g_sa [(size_t)B_ * N_ * D_];         // [b][n][h*hd+d]
__device__ __half g_xt [(size_t)MROWS * D_];           // x -> fp16
__device__ __half g_wt_kqv[(size_t)H_ * E3_ * D_];     // W_kqv^T [h][e][k]
__device__ __half g_wt_proj[(size_t)D_ * D_];          // W_proj^T [n][k]

// ---------------------------------------------------------------------------
// Helpers
// ---------------------------------------------------------------------------
__device__ __forceinline__ float ex2(float x) {
    float y;
    asm("ex2.approx.f32 %0, %1;" : "=f"(y) : "f"(x));
    return y;
}
__device__ __forceinline__ void cpa16(uint32_t dst, const void* src) {
    asm volatile("cp.async.ca.shared.global [%0], [%1], 16;" :: "r"(dst), "l"(src));
}
__device__ __forceinline__ uint32_t smem_u32(const void* p) {
    uint32_t a;
    asm("{ .reg .u64 t; cvta.to.shared.u64 t, %1; cvt.u32.u64 %0, t; }"
        : "=r"(a) : "l"(p));
    return a;
}
__device__ __forceinline__ void mma_f16(float* c, const uint32_t* a, const uint32_t* b) {
    asm volatile(
        "mma.sync.aligned.m16n8k16.row.col.f32.f16.f16.f32 "
        "{%0,%1,%2,%3}, {%4,%5,%6,%7}, {%8,%9}, {%0,%1,%2,%3};"
        : "+f"(c[0]), "+f"(c[1]), "+f"(c[2]), "+f"(c[3])
        : "r"(a[0]), "r"(a[1]), "r"(a[2]), "r"(a[3]), "r"(b[0]), "r"(b[1]));
}
__device__ __forceinline__ void ldsm4(uint32_t* r, uint32_t addr) {
    asm volatile(
        "ldmatrix.sync.aligned.m8n8.x4.shared.b16 {%0,%1,%2,%3}, [%4];"
        : "=r"(r[0]), "=r"(r[1]), "=r"(r[2]), "=r"(r[3]) : "r"(addr));
}
__device__ __forceinline__ void ldsm4t(uint32_t* r, uint32_t addr) {
    asm volatile(
        "ldmatrix.sync.aligned.m8n8.x4.trans.shared.b16 {%0,%1,%2,%3}, [%4];"
        : "=r"(r[0]), "=r"(r[1]), "=r"(r[2]), "=r"(r[3]) : "r"(addr));
}
__device__ __forceinline__ uint32_t packh2(float x, float y) {
    __half2 h = __floats2half2_rn(x, y);
    return *(uint32_t*)&h;
}
__device__ __forceinline__ void mbar_wait(uint32_t mbar, uint32_t parity) {
    uint32_t done;
    asm volatile(
        "{\n\t.reg .pred p;\n\t"
        "mbarrier.try_wait.parity.acquire.cta.shared::cta.b64 p, [%1], %2;\n\t"
        "selp.b32 %0, 1, 0, p;\n\t}"
        : "=r"(done) : "r"(mbar), "r"(parity) : "memory");
    while (!done) {
        asm volatile(
            "{\n\t.reg .pred p;\n\t"
            "mbarrier.try_wait.parity.acquire.cta.shared::cta.b64 p, [%1], %2, 0x989680;\n\t"
            "selp.b32 %0, 1, 0, p;\n\t}"
            : "=r"(done) : "r"(mbar), "r"(parity) : "memory");
    }
}

// ---------------------------------------------------------------------------
// Merged prep kernel: fp16-convert x + transpose/convert both weights.
// ---------------------------------------------------------------------------
#define PREP_X   (MROWS * D_ / 1024)          // 8192 blocks
#define PREP_KQV (32 * (E3_ / 32) * H_)       // 3072 blocks
#define PREP_PRJ (32 * 32)                    // 1024 blocks

__global__ void prep_kernel(const float* __restrict__ x,
                            const float* __restrict__ Wkqv,
                            const float* __restrict__ Wproj)
{
    __shared__ float t[32][33];
    const int bx = blockIdx.x, tid = threadIdx.x;
    if (bx < PREP_X) {
        size_t i = ((size_t)bx * 256 + tid) * 4;
        float4 v = *(const float4*)(x + i);
        __half2* dst = (__half2*)(g_xt + i);
        dst[0] = __floats2half2_rn(v.x, v.y);
        dst[1] = __floats2half2_rn(v.z, v.w);
    } else if (bx < PREP_X + PREP_KQV) {
        const int bid = bx - PREP_X;
        const int k0 = (bid & 31) * 32;
        const int e0 = ((bid >> 5) % (E3_ / 32)) * 32;
        const int h  = bid / (32 * (E3_ / 32));
        const float* Wh = Wkqv + (size_t)h * D_ * E3_;
        __half* Wt = g_wt_kqv + (size_t)h * E3_ * D_;
        const int xx = tid & 31, yy = tid >> 5;
#pragma unroll
        for (int j = 0; j < 32; j += 8)
            t[yy + j][xx] = Wh[(size_t)(k0 + yy + j) * E3_ + e0 + xx];
        __syncthreads();
#pragma unroll
        for (int j = 0; j < 32; j += 8)
            Wt[(size_t)(e0 + yy + j) * D_ + k0 + xx] = __float2half_rn(t[xx][yy + j]);
    } else {
        const int bid = bx - PREP_X - PREP_KQV;
        const int k0 = (bid & 31) * 32;
        const int n0 = (bid >> 5) * 32;
        const int xx = tid & 31, yy = tid >> 5;
#pragma unroll
        for (int j = 0; j < 32; j += 8)
            t[yy + j][xx] = Wproj[(size_t)(k0 + yy + j) * D_ + n0 + xx];
        __syncthreads();
#pragma unroll
        for (int j = 0; j < 32; j += 8)
            g_wt_proj[(size_t)(n0 + yy + j) * D_ + k0 + xx] = __float2half_rn(t[xx][yy + j]);
    }
}

// ---------------------------------------------------------------------------
// fp16 mma GEMM, 512 threads (16 warps = 4M x 4N), CTA tile 128 x NT.
// (unchanged from R13)
// ---------------------------------------------------------------------------
template <int NT, int PER_HEAD>
__global__ __launch_bounds__(512, 1) void gemm_mma_kernel(
    const float* __restrict__ bias, float* __restrict__ Cout)
{
    constexpr int NSUBW = NT / 32;
    constexpr int AST = 128 * 72;
    constexpr int BST = NT * 72;
    extern __shared__ __half smh[];
    __half* As = smh;
    __half* Bs = smh + 3 * AST;

    const int tid  = threadIdx.x;
    const int m0   = blockIdx.x * 128;
    const int head = blockIdx.y;
    const int n0   = PER_HEAD ? 0 : blockIdx.y * NT;

    const __half* Ab = (PER_HEAD ? g_xt : g_sa) + (size_t)m0 * D_;
    const __half* Bt = PER_HEAD ? (g_wt_kqv + (size_t)head * E3_ * D_)
                                : (g_wt_proj + (size_t)n0 * D_);

    const uint32_t sA = smem_u32(As);
    const uint32_t sB = smem_u32(Bs);

    auto load_stage = [&](int kc, int buf) {
        const __half* ap = Ab + kc * 64;
        const uint32_t da = sA + (uint32_t)buf * AST * 2;
#pragma unroll
        for (int j = 0; j < 2; ++j) {
            const int idx = tid + j * 512;
            const int r = idx >> 3, q = (idx & 7) << 3;
            cpa16(da + (uint32_t)(r * 72 + q) * 2, ap + (size_t)r * D_ + q);
        }
        const __half* bp = Bt + kc * 64;
        const uint32_t db = sB + (uint32_t)buf * BST * 2;
#pragma unroll
        for (int j = 0; j < NT / 64; ++j) {
            const int idx = tid + j * 512;
            const int r = idx >> 3, q = (idx & 7) << 3;
            cpa16(db + (uint32_t)(r * 72 + q) * 2, bp + (size_t)r * D_ + q);
        }
    };

    const int w    = tid >> 5, lane = tid & 31;
    const int wm   = (w & 3) * 32;
    const int wn   = (w >> 2) * (NT / 4);
    const int grp  = lane >> 2, tig = lane & 3;

    const int lrA = ((lane >> 3) & 1) * 8 + (lane & 7);
    const int lcA = ((lane >> 4) & 1) * 8;
    const int lrB = ((lane >> 4) & 1) * 8 + (lane & 7);
    const int lcB = ((lane >> 3) & 1) * 8;

    float acc[2][NSUBW][4];
#pragma unroll
    for (int mi = 0; mi < 2; ++mi)
#pragma unroll
        for (int ni = 0; ni < NSUBW; ++ni)
#pragma unroll
            for (int r = 0; r < 4; ++r) acc[mi][ni][r] = 0.f;

    load_stage(0, 0);
    asm volatile("cp.async.commit_group;" ::: "memory");
    load_stage(1, 1);
    asm volatile("cp.async.commit_group;" ::: "memory");

    for (int kc = 0; kc < 16; ++kc) {
        asm volatile("cp.async.wait_group 1;" ::: "memory");
        __syncthreads();
        if (kc + 2 < 16) load_stage(kc + 2, (kc + 2) % 3);
        asm volatile("cp.async.commit_group;" ::: "memory");

        const int st = kc % 3;
        const uint32_t uAp = sA + (uint32_t)st * AST * 2;
        const uint32_t uBp = sB + (uint32_t)st * BST * 2;
#pragma unroll
        for (int ks = 0; ks < 4; ++ks) {
            const int k = ks * 16;
            uint32_t a[2][4], bf[NSUBW][2];
#pragma unroll
            for (int mi = 0; mi < 2; ++mi)
                ldsm4(a[mi], uAp + (uint32_t)((wm + mi * 16 + lrA) * 72 + k + lcA) * 2);
#pragma unroll
            for (int np = 0; np < NSUBW / 2; ++np) {
                uint32_t r[4];
                ldsm4(r, uBp + (uint32_t)((wn + np * 16 + lrB) * 72 + k + lcB) * 2);
                bf[2 * np][0] = r[0]; bf[2 * np][1] = r[1];
                bf[2 * np + 1][0] = r[2]; bf[2 * np + 1][1] = r[3];
            }
#pragma unroll
            for (int mi = 0; mi < 2; ++mi)
#pragma unroll
                for (int ni = 0; ni < NSUBW; ++ni)
                    mma_f16(acc[mi][ni], a[mi], bf[ni]);
        }
    }

#pragma unroll
    for (int mi = 0; mi < 2; ++mi) {
        const int mbase = m0 + wm + mi * 16 + grp;
#pragma unroll
        for (int half = 0; half < 2; ++half) {
            const int m = mbase + half * 8;
#pragma unroll
            for (int ni = 0; ni < NSUBW; ++ni) {
                const int c = wn + ni * 8 + 2 * tig;
                const float vx = acc[mi][ni][half * 2 + 0];
                const float vy = acc[mi][ni][half * 2 + 1];
                if (PER_HEAD) {
                    const int b = m >> 11, tok = m & 2047;
                    __half* dst = g_kqv + (((size_t)b * H_ + head) * N_ + tok) * E3_;
                    const float* bsp = bias + head * E3_;
                    *(__half2*)(dst + c) =
                        __floats2half2_rn(vx + bsp[c], vy + bsp[c + 1]);
                } else {
                    float* dst = Cout + (size_t)m * D_ + n0;
                    const float* bsp = bias + n0;
                    float2 o; o.x = vx + bsp[c]; o.y = vy + bsp[c + 1];
                    *(float2*)(dst + c) = o;
                }
            }
        }
    }
}

// ---------------------------------------------------------------------------
// fp16 tensor-core causal flash attention — register-P, BM=256.
// 8 warps x 32 Q-rows: each warp's K/V ldmatrix reads now feed 128 mma
// instead of 64 (LDSM/mma 0.5 -> 0.25), moving tiles from smem-port-bound
// to tensor-bound. Ring/mbarrier protocol identical to R13.
// ---------------------------------------------------------------------------
#define BM 256
#define BK 64
#define KSTH (64 * 72)     // K or V tile (halves)
#define QSTH (BM * 72)     // Q staging (halves)
#define KRING 4
#define VRING 4

__global__ __launch_bounds__(256, 1) void attn_mma_kernel()
{
    extern __shared__ __half smh[];
    const uint32_t sb  = smem_u32(smh);
    const uint32_t uMb = sb;                         // 4 mbarriers
    const uint32_t uKb = sb + 64;                    // [KRING][KSTH]
    const uint32_t uVb = uKb + KRING * KSTH * 2;     // [VRING][KSTH]
    const uint32_t uQ  = uVb + VRING * KSTH * 2;     // [QSTH]

    const int qi  = (int)(gridDim.x - 1 - blockIdx.x);  // heavy tiles first
    const int h   = blockIdx.y, b = blockIdx.z;
    const int tid = threadIdx.x;
    const int w   = tid >> 5, lane = tid & 31;
    const int grp = lane >> 2, tig = lane & 3;
    const int m0  = qi * BM;
    const int wbase = w * 32;
    const size_t base = ((size_t)b * H_ + h) * N_ * E3_;

    const int lrA = ((lane >> 3) & 1) * 8 + (lane & 7);
    const int lcA = ((lane >> 4) & 1) * 8;
    const int lrB = ((lane >> 4) & 1) * 8 + (lane & 7);
    const int lcB = ((lane >> 3) & 1) * 8;

    const int nt = (m0 + BM) / BK;

    if (tid < KRING) {
        asm volatile("mbarrier.init.shared.b64 [%0], 256;"
                     :: "r"(uMb + (uint32_t)(tid * 8)) : "memory");
    }
    __syncthreads();

    auto load_kv = [&](int kt) {
        const __half* kp = g_kqv + base + (size_t)(kt * BK) * E3_;
        const uint32_t kd = uKb + (uint32_t)(kt % KRING) * KSTH * 2;
#pragma unroll
        for (int j = 0; j < 2; ++j) {
            const int i = tid + j * 256;
            const int n = i >> 3, c = (i & 7) << 3;
            cpa16(kd + (uint32_t)(n * 72 + c) * 2, kp + (size_t)n * E3_ + c);
        }
        const __half* vp = kp + 2 * HD_;
        const uint32_t vd = uVb + (uint32_t)(kt % VRING) * KSTH * 2;
#pragma unroll
        for (int j = 0; j < 2; ++j) {
            const int i = tid + j * 256;
            const int n = i >> 3, c = (i & 7) << 3;
            cpa16(vd + (uint32_t)(n * 72 + c) * 2, vp + (size_t)n * E3_ + c);
        }
        asm volatile("cp.async.mbarrier.arrive.noinc.shared.b64 [%0];"
                     :: "r"(uMb + (uint32_t)((kt % KRING) * 8)) : "memory");
    };

    // Stage Q (256 x 64 halves) + prefetch tiles 0,1
    {
        const __half* q0 = g_kqv + base + (size_t)m0 * E3_ + HD_;
#pragma unroll
        for (int j = 0; j < 8; ++j) {
            const int i = tid + j * 256;
            const int r = i >> 3, c = (i & 7) << 3;
            cpa16(uQ + (uint32_t)(r * 72 + c) * 2, q0 + (size_t)r * E3_ + c);
        }
    }
    load_kv(0);
    if (1 < nt) load_kv(1);
    asm volatile("cp.async.commit_group;" ::: "memory");
    asm volatile("cp.async.wait_group 0;" ::: "memory");
    __syncthreads();

    // Q fragments (unscaled) in registers for the whole kernel: 2 m-frags
    uint32_t qf[2][4][4];
#pragma unroll
    for (int mi = 0; mi < 2; ++mi) {
        const uint32_t uQw = uQ + (uint32_t)((wbase + mi * 16 + lrA) * 72) * 2;
#pragma unroll
        for (int ks = 0; ks < 4; ++ks)
            ldsm4(qf[mi][ks], uQw + (uint32_t)(ks * 16 + lcA) * 2);
    }

    const int rw0   = m0 + wbase + grp;      // row of (mi=0, half=0)
    const int rmax  = m0 + wbase + 31;
    const int diag0 = m0 / BK;

    float oacc[2][8][4];
#pragma unroll
    for (int mi = 0; mi < 2; ++mi)
#pragma unroll
        for (int ni = 0; ni < 8; ++ni)
#pragma unroll
            for (int r = 0; r < 4; ++r) oacc[mi][ni][r] = 0.f;
    float mr[2][2] = {{NEG_INF, NEG_INF}, {NEG_INF, NEG_INF}};
    float lr[2][2] = {{0.f, 0.f}, {0.f, 0.f}};

    for (int kt = 0; kt < nt; ++kt) {
        if ((kt & 1) == 0) __syncthreads();   // bound warp drift <= 1 iter
        if (kt + 2 < nt) load_kv(kt + 2);
        mbar_wait(uMb + (uint32_t)((kt % KRING) * 8), (uint32_t)((kt >> 2) & 1));

        if (kt * BK > rmax) continue;   // fully masked tile

        // S = Q K^T  (both m-frags share each B fragment)
        const uint32_t uKp = uKb + (uint32_t)(kt % KRING) * KSTH * 2;
        float s[2][8][4];
#pragma unroll
        for (int mi = 0; mi < 2; ++mi)
#pragma unroll
            for (int ni = 0; ni < 8; ++ni)
#pragma unroll
                for (int r = 0; r < 4; ++r) s[mi][ni][r] = 0.f;
#pragma unroll
        for (int ks = 0; ks < 4; ++ks) {
            const int k = ks * 16;
            uint32_t bf[8][2];
#pragma unroll
            for (int np = 0; np < 4; ++np) {
                uint32_t r[4];
                ldsm4(r, uKp + (uint32_t)((np * 16 + lrB) * 72 + k + lcB) * 2);
                bf[2 * np][0] = r[0]; bf[2 * np][1] = r[1];
                bf[2 * np + 1][0] = r[2]; bf[2 * np + 1][1] = r[3];
            }
#pragma unroll
            for (int mi = 0; mi < 2; ++mi)
#pragma unroll
                for (int ni = 0; ni < 8; ++ni)
                    mma_f16(s[mi][ni], qf[mi][ks], bf[ni]);
        }

        // Causal mask (diagonal-overlapping tiles only)
        if (kt >= diag0) {
            const int colb = kt * BK;
#pragma unroll
            for (int mi = 0; mi < 2; ++mi) {
                const int ra = rw0 + mi * 16, rb = ra + 8;
#pragma unroll
                for (int ni = 0; ni < 8; ++ni) {
                    const int c = colb + ni * 8 + 2 * tig;
                    if (c > ra)     s[mi][ni][0] = NEG_INF;
                    if (c + 1 > ra) s[mi][ni][1] = NEG_INF;
                    if (c > rb)     s[mi][ni][2] = NEG_INF;
                    if (c + 1 > rb) s[mi][ni][3] = NEG_INF;
                }
            }
        }

        // Online softmax for 4 row-groups (mi, half)
        float alpha[2][2];
#pragma unroll
        for (int mi = 0; mi < 2; ++mi) {
            float mx0 = NEG_INF, mx1 = NEG_INF;
#pragma unroll
            for (int ni = 0; ni < 8; ++ni) {
                mx0 = fmaxf(mx0, fmaxf(s[mi][ni][0], s[mi][ni][1]));
                mx1 = fmaxf(mx1, fmaxf(s[mi][ni][2], s[mi][ni][3]));
            }
            mx0 = fmaxf(mx0, __shfl_xor_sync(0xffffffffu, mx0, 1));
            mx0 = fmaxf(mx0, __shfl_xor_sync(0xffffffffu, mx0, 2));
            mx1 = fmaxf(mx1, __shfl_xor_sync(0xffffffffu, mx1, 1));
            mx1 = fmaxf(mx1, __shfl_xor_sync(0xffffffffu, mx1, 2));

            const float mn0 = fmaxf(mr[mi][0], mx0 * QSCALE);
            const float mn1 = fmaxf(mr[mi][1], mx1 * QSCALE);
            alpha[mi][0] = ex2(mr[mi][0] - mn0);
            alpha[mi][1] = ex2(mr[mi][1] - mn1);
            float sum0 = 0.f, sum1 = 0.f;
#pragma unroll
            for (int ni = 0; ni < 8; ++ni) {
                s[mi][ni][0] = ex2(fmaf(s[mi][ni][0], QSCALE, -mn0));
                s[mi][ni][1] = ex2(fmaf(s[mi][ni][1], QSCALE, -mn0));
                s[mi][ni][2] = ex2(fmaf(s[mi][ni][2], QSCALE, -mn1));
                s[mi][ni][3] = ex2(fmaf(s[mi][ni][3], QSCALE, -mn1));
                sum0 += s[mi][ni][0] + s[mi][ni][1];
                sum1 += s[mi][ni][2] + s[mi][ni][3];
            }
            sum0 += __shfl_xor_sync(0xffffffffu, sum0, 1);
            sum0 += __shfl_xor_sync(0xffffffffu, sum0, 2);
            sum1 += __shfl_xor_sync(0xffffffffu, sum1, 1);
            sum1 += __shfl_xor_sync(0xffffffffu, sum1, 2);

            lr[mi][0] = lr[mi][0] * alpha[mi][0] + sum0;  mr[mi][0] = mn0;
            lr[mi][1] = lr[mi][1] * alpha[mi][1] + sum1;  mr[mi][1] = mn1;
#pragma unroll
            for (int ni = 0; ni < 8; ++ni) {
                oacc[mi][ni][0] *= alpha[mi][0]; oacc[mi][ni][1] *= alpha[mi][0];
                oacc[mi][ni][2] *= alpha[mi][1]; oacc[mi][ni][3] *= alpha[mi][1];
            }
        }

        // O += P V : P A-fragments in registers; V B-frags shared by both mi
        const uint32_t uVp = uVb + (uint32_t)(kt % VRING) * KSTH * 2;
#pragma unroll
        for (int ks = 0; ks < 4; ++ks) {
            const int k = ks * 16;
            uint32_t bf[8][2];
#pragma unroll
            for (int np = 0; np < 4; ++np) {
                uint32_t r[4];
                ldsm4t(r, uVp + (uint32_t)((k + lrA) * 72 + np * 16 + lcA) * 2);
                bf[2 * np][0] = r[0]; bf[2 * np][1] = r[1];
                bf[2 * np + 1][0] = r[2]; bf[2 * np + 1][1] = r[3];
            }
#pragma unroll
            for (int mi = 0; mi < 2; ++mi) {
                uint32_t a[4];
                a[0] = packh2(s[mi][2 * ks][0],     s[mi][2 * ks][1]);
                a[1] = packh2(s[mi][2 * ks][2],     s[mi][2 * ks][3]);
                a[2] = packh2(s[mi][2 * ks + 1][0], s[mi][2 * ks + 1][1]);
                a[3] = packh2(s[mi][2 * ks + 1][2], s[mi][2 * ks + 1][3]);
#pragma unroll
                for (int ni = 0; ni < 8; ++ni)
                    mma_f16(oacc[mi][ni], a, bf[ni]);
            }
        }
    }

    // Epilogue: normalize, fp16-store (proj GEMM consumes g_sa)
#pragma unroll
    for (int mi = 0; mi < 2; ++mi) {
        const float inv0 = 1.0f / lr[mi][0], inv1 = 1.0f / lr[mi][1];
        const int ra = rw0 + mi * 16, rb = ra + 8;
        __half* d0 = g_sa + ((size_t)b * N_ + ra) * D_ + h * HD_;
        __half* d1 = g_sa + ((size_t)b * N_ + rb) * D_ + h * HD_;
#pragma unroll
        for (int ni = 0; ni < 8; ++ni) {
            const int c = ni * 8 + 2 * tig;
            *(__half2*)(d0 + c) =
                __floats2half2_rn(oacc[mi][ni][0] * inv0, oacc[mi][ni][1] * inv0);
            *(__half2*)(d1 + c) =
                __floats2half2_rn(oacc[mi][ni][2] * inv1, oacc[mi][ni][3] * inv1);
        }
    }
}

// ---------------------------------------------------------------------------
extern "C" void kernel_launch(void* const* d_in, const int* in_sizes, int n_in,
                              void* d_out, int out_size)
{
    const float* x      = (const float*)d_in[0];
    const float* W_kqv  = (const float*)d_in[1];
    const float* b_kqv  = (const float*)d_in[2];
    const float* W_proj = (const float*)d_in[3];
    const float* b_proj = (const float*)d_in[4];
    float* out = (float*)d_out;

    const int SMEM_Q = 3 * (128 + E3_) * 72 * 2;                     // 138240
    const int SMEM_P = 3 * (128 + 128) * 72 * 2;                     // 110592
    const int SMEM_A = 64 + ((KRING + VRING) * KSTH + QSTH) * 2;     // 184384
    cudaFuncSetAttribute(gemm_mma_kernel<E3_, 1>,
                         cudaFuncAttributeMaxDynamicSharedMemorySize, SMEM_Q);
    cudaFuncSetAttribute(gemm_mma_kernel<128, 0>,
                         cudaFuncAttributeMaxDynamicSharedMemorySize, SMEM_P);
    cudaFuncSetAttribute(attn_mma_kernel,
                         cudaFuncAttributeMaxDynamicSharedMemorySize, SMEM_A);

    prep_kernel<<<PREP_X + PREP_KQV + PREP_PRJ, 256>>>(x, W_kqv, W_proj);

    gemm_mma_kernel<E3_, 1><<<dim3(MROWS / 128, H_), 512, SMEM_Q>>>(b_kqv, nullptr);
    attn_mma_kernel<<<dim3(N_ / BM, H_, B_), 256, SMEM_A>>>();
    gemm_mma_kernel<128, 0><<<dim3(MROWS / 128, D_ / 128), 512, SMEM_P>>>(b_proj, out);
}